// round 10
// baseline (speedup 1.0000x reference)
#include <cuda_runtime.h>
#include <cuda_bf16.h>

typedef unsigned long long u64;

#define NG   256
#define NN   64
#define KNN  24
#define HID  128
#define NPAD 132   // float stride for fp32 64x128 tiles
#define DPAD 68    // uint stride for 64x64 key matrix
#define XPS  66    // u32 stride for packed bf16 planes
#define NT   512   // threads per CTA

// fragment-ordered bf16 edge weights: [part 2][split 2][kstep 8][ntile 16][lane 32][2] u32
__device__ __align__(16) unsigned g_Wfe[2 * 2 * 8 * 16 * 32 * 2];
// k-pair-packed fp32 weights for stage 1
__device__ u64 g_W2p[64 * 128];
__device__ u64 g_W1p[8 * 128];    // K=15 zero-padded to 16

__device__ __forceinline__ void fma2(u64& d, u64 a, u64 b) {
    asm("fma.rn.f32x2 %0, %1, %2, %0;" : "+l"(d) : "l"(a), "l"(b));
}
__device__ __forceinline__ float2 upk(u64 v) {
    float2 f; asm("mov.b64 {%0, %1}, %2;" : "=f"(f.x), "=f"(f.y) : "l"(v)); return f;
}
__device__ __forceinline__ u64 pk(float lo, float hi) {
    u64 r; asm("mov.b64 %0, {%1, %2};" : "=l"(r) : "f"(lo), "f"(hi)); return r;
}
__device__ __forceinline__ float hadd(u64 v) {
    float2 f = upk(v); return f.x + f.y;
}
__device__ __forceinline__ float elu1(float x) {
    return x > 0.f ? x : (__expf(x) - 1.f);
}
__device__ __forceinline__ unsigned fkey(float d) {
    unsigned u = __float_as_uint(d);
    return ((int)u < 0) ? ~u : (u | 0x80000000u);
}
__device__ __forceinline__ unsigned pkbf2(float a, float b) {
    __nv_bfloat162 h = __floats2bfloat162_rn(a, b);
    return *reinterpret_cast<unsigned*>(&h);
}
__device__ __forceinline__ float bf16f(float v) {
    return __bfloat162float(__float2bfloat16_rn(v));
}

__device__ __forceinline__ void mma_bf16(float* c, const unsigned* a, unsigned b0, unsigned b1) {
    asm volatile("mma.sync.aligned.m16n8k16.row.col.f32.bf16.bf16.f32 "
        "{%0,%1,%2,%3}, {%4,%5,%6,%7}, {%8,%9}, {%0,%1,%2,%3};\n"
        : "+f"(c[0]), "+f"(c[1]), "+f"(c[2]), "+f"(c[3])
        : "r"(a[0]), "r"(a[1]), "r"(a[2]), "r"(a[3]), "r"(b0), "r"(b1));
}

// Wcat(k, cc): cc<128 -> Wc_top - Wc_bot ('a' weights); else Wc_bot ('p' weights)
__device__ __forceinline__ float wcat(const float* Wc, int k, int cc) {
    if (cc < HID) return Wc[k * HID + cc] - Wc[(HID + k) * HID + cc];
    return Wc[(HID + k) * HID + (cc - HID)];
}

__global__ void prep_kernel(const float* __restrict__ Wc,
                            const float* __restrict__ W1,
                            const float* __restrict__ W2) {
    int i = blockIdx.x * blockDim.x + threadIdx.x;
    if (i < 32768) {
        int r = i & 1, L = (i >> 1) & 31, nt = (i >> 6) & 15;
        int ks = (i >> 10) & 7, sp = (i >> 13) & 1, part = (i >> 14) & 1;
        int c  = nt * 8 + (L >> 2);
        int k0 = ks * 16 + (L & 3) * 2 + r * 8;
        int cc = part * HID + c;
        float v0 = wcat(Wc, k0, cc);
        float v1 = wcat(Wc, k0 + 1, cc);
        unsigned u;
        if (sp == 0) u = pkbf2(v0, v1);
        else         u = pkbf2(v0 - bf16f(v0), v1 - bf16f(v1));
        g_Wfe[i] = u;
    }
    int j = i - 32768;
    if (j >= 0 && j < 64 * 128) {
        int kp = j >> 7, c = j & 127;
        g_W2p[j] = pk(W2[(2 * kp) * HID + c], W2[(2 * kp + 1) * HID + c]);
    }
    int l = i - 32768 - 64 * 128;
    if (l >= 0 && l < 8 * 128) {
        int kp = l >> 7, c = l & 127;
        float lo = W1[(2 * kp) * HID + c];
        float hi = (2 * kp + 1 < 15) ? W1[(2 * kp + 1) * HID + c] : 0.f;
        g_W1p[l] = pk(lo, hi);
    }
}

// Out[64x128] = elu( Xin[64 x 2*KP] @ W + bias ). Uses threads 0-255 (8 warps), 8 rows x 4 cols.
__device__ __forceinline__ void gemm_act(const float* __restrict__ Xin, int xs, int KP,
                                         const u64* __restrict__ Wp,
                                         const float* __restrict__ bias,
                                         float* __restrict__ Out, int t) {
    int n0 = (t >> 5) * 8;
    int c0 = (t & 31) * 4;
    u64 acc[8][4];
#pragma unroll
    for (int i = 0; i < 8; i++) { acc[i][0] = 0; acc[i][1] = 0; acc[i][2] = 0; acc[i][3] = 0; }
#pragma unroll 4
    for (int kp = 0; kp < KP; kp++) {
        const u64* wr = Wp + kp * 128 + c0;
        ulonglong2 wa = *(const ulonglong2*)(wr);
        ulonglong2 wb = *(const ulonglong2*)(wr + 2);
        u64 xv[8];
#pragma unroll
        for (int i = 0; i < 8; i++) xv[i] = *(const u64*)(Xin + (n0 + i) * xs + 2 * kp);
#pragma unroll
        for (int i = 0; i < 8; i++) {
            fma2(acc[i][0], xv[i], wa.x);
            fma2(acc[i][1], xv[i], wa.y);
            fma2(acc[i][2], xv[i], wb.x);
            fma2(acc[i][3], xv[i], wb.y);
        }
    }
    float4 b = *(const float4*)(bias + c0);
#pragma unroll
    for (int i = 0; i < 8; i++) {
        float4 r;
        r.x = elu1(hadd(acc[i][0]) + b.x);
        r.y = elu1(hadd(acc[i][1]) + b.y);
        r.z = elu1(hadd(acc[i][2]) + b.z);
        r.w = elu1(hadd(acc[i][3]) + b.w);
        *(float4*)(Out + (n0 + i) * NPAD + c0) = r;
    }
}

// Distance Gram on tensor cores (4-term bf16 split). 16 warps: rows 16*(w&3), cols 16*(w>>2).
// Writes fkey(d) into dsu (Xs window).
__device__ __forceinline__ void dist_mma(const unsigned* __restrict__ Xp,
                                         const float* __restrict__ sq,
                                         unsigned* __restrict__ dsu, int t) {
    int w = t >> 5, L = t & 31;
    int m0 = (w & 3) * 16;
    int nbase = (w >> 2) * 16;
    const unsigned* xh = Xp + (m0 + (L >> 2)) * XPS + (L & 3);
    const unsigned* xl = xh + 64 * XPS;
    const unsigned* bbase = Xp + (nbase + (L >> 2)) * XPS + (L & 3);
    float acc[2][4];
#pragma unroll
    for (int nt = 0; nt < 2; nt++) {
        acc[nt][0] = 0.f; acc[nt][1] = 0.f; acc[nt][2] = 0.f; acc[nt][3] = 0.f;
    }
#pragma unroll
    for (int ks = 0; ks < 8; ks++) {
        unsigned ah[4], al[4];
        ah[0] = xh[ks * 8];         ah[1] = xh[8 * XPS + ks * 8];
        ah[2] = xh[ks * 8 + 4];     ah[3] = xh[8 * XPS + ks * 8 + 4];
        al[0] = xl[ks * 8];         al[1] = xl[8 * XPS + ks * 8];
        al[2] = xl[ks * 8 + 4];     al[3] = xl[8 * XPS + ks * 8 + 4];
#pragma unroll
        for (int nt = 0; nt < 2; nt++) {
            const unsigned* bh = bbase + nt * 8 * XPS + ks * 8;
            const unsigned* bl = bh + 64 * XPS;
            unsigned bh0 = bh[0], bh1 = bh[4];
            unsigned bl0 = bl[0], bl1 = bl[4];
            mma_bf16(acc[nt], ah, bh0, bh1);
            mma_bf16(acc[nt], ah, bl0, bl1);
            mma_bf16(acc[nt], al, bh0, bh1);
            mma_bf16(acc[nt], al, bl0, bl1);
        }
    }
    int r0 = m0 + (L >> 2);
    float si0 = sq[r0], si1 = sq[r0 + 8];
#pragma unroll
    for (int nt = 0; nt < 2; nt++) {
        int c0 = nbase + nt * 8 + (L & 3) * 2;
        float sj0 = sq[c0], sj1 = sq[c0 + 1];
        dsu[r0 * DPAD + c0]           = fkey(si0 + sj0 - 2.f * acc[nt][0]);
        dsu[r0 * DPAD + c0 + 1]       = fkey(si0 + sj1 - 2.f * acc[nt][1]);
        dsu[(r0 + 8) * DPAD + c0]     = fkey(si1 + sj0 - 2.f * acc[nt][2]);
        dsu[(r0 + 8) * DPAD + c0 + 1] = fkey(si1 + sj1 - 2.f * acc[nt][3]);
    }
}

// Edge gemm on tensor cores (3-term bf16 split). 16 warps:
// part = w>>3, rows 16*(w&3), ntile half ((w>>2)&1)*8. Internal barrier before epilogue.
__device__ __forceinline__ void gemm_edge_mma(const unsigned* __restrict__ Xp,
                                              float* __restrict__ Aout,
                                              float* __restrict__ Pout, int t) {
    int w = t >> 5, L = t & 31;
    int part = w >> 3;
    int m0 = (w & 3) * 16;
    int nt0 = ((w >> 2) & 1) * 8;
    const unsigned* xh = Xp + (m0 + (L >> 2)) * XPS + (L & 3);
    const unsigned* xl = xh + 64 * XPS;
    float acc[8][4];
#pragma unroll
    for (int q = 0; q < 8; q++) {
        acc[q][0] = 0.f; acc[q][1] = 0.f; acc[q][2] = 0.f; acc[q][3] = 0.f;
    }
    const unsigned* wb = g_Wfe + part * 16384 + L * 2;
#pragma unroll
    for (int ks = 0; ks < 8; ks++) {
        unsigned ah[4], al[4];
        ah[0] = xh[ks * 8];         ah[1] = xh[8 * XPS + ks * 8];
        ah[2] = xh[ks * 8 + 4];     ah[3] = xh[8 * XPS + ks * 8 + 4];
        al[0] = xl[ks * 8];         al[1] = xl[8 * XPS + ks * 8];
        al[2] = xl[ks * 8 + 4];     al[3] = xl[8 * XPS + ks * 8 + 4];
#pragma unroll
        for (int q = 0; q < 8; q++) {
            const unsigned* wp = wb + (ks * 16 + nt0 + q) * 64;
            uint2 bh = *(const uint2*)(wp);
            uint2 bl = *(const uint2*)(wp + 8192);
            mma_bf16(acc[q], ah, bh.x, bh.y);   // hi*hi
            mma_bf16(acc[q], ah, bl.x, bl.y);   // hi*lo
            mma_bf16(acc[q], al, bh.x, bh.y);   // lo*hi
        }
    }
    __syncthreads();   // all Xp reads (dist + edge) done; safe to overwrite Ap/Ps
    float* dst = part ? Pout : Aout;
    int row = m0 + (L >> 2);
    int col0 = (L & 3) * 2;
#pragma unroll
    for (int q = 0; q < 8; q++) {
        int nt = nt0 + q;
        *(float2*)(dst + row * NPAD + nt * 8 + col0)       = make_float2(acc[q][0], acc[q][1]);
        *(float2*)(dst + (row + 8) * NPAD + nt * 8 + col0) = make_float2(acc[q][2], acc[q][3]);
    }
}

// smem layout (floats)
#define OFF_XS  0                      // Xs fp32 features / distance keys
#define OFF_AP  (NN * NPAD)            // Ap: 'a' fp32 / bf16 Xp planes / Xi scratch
#define OFF_PS  (2 * NN * NPAD)        // Ps: 'p' fp32 / h1 scratch
#define OFF_IDX (3 * NN * NPAD)
#define SMEM_FLOATS (OFF_IDX + NN * KNN + NN + 256)

__global__ __launch_bounds__(NT, 2)
void net_kernel(const float* __restrict__ x_pf,
                const float* __restrict__ b1, const float* __restrict__ b2,
                const float* __restrict__ bc,
                const float* __restrict__ Wo1, const float* __restrict__ bo1,
                const float* __restrict__ Wo2, const float* __restrict__ bo2,
                const float* __restrict__ Wo3, const float* __restrict__ bo3,
                const float* __restrict__ Wo4, const float* __restrict__ bo4,
                float* __restrict__ out, int write_batch) {
    extern __shared__ __align__(16) float sm[];
    float* Xs = sm + OFF_XS;
    float* Ap = sm + OFF_AP;
    float* Ps = sm + OFF_PS;
    int*   idxs = (int*)(sm + OFF_IDX);
    float* sq = sm + OFF_IDX + NN * KNN;
    float* hd = sq + NN;
    unsigned* dsu = (unsigned*)Xs;     // distance keys in Xs window (fp32 X dead after convert)
    unsigned* Xp  = (unsigned*)Ap;     // bf16 planes in Ap window

    int g = blockIdx.x;
    int t = threadIdx.x;

    // ---------------- Stage 1: h = elu(elu(x@W1+b1)@W2+b2) ----------------
    float* Xi = Ap;  // temp [64][16], col 15 zeroed
    for (int i = t; i < NN * 16; i += NT) {
        int n = i >> 4, f = i & 15;
        Xi[i] = (f < 15) ? x_pf[(g * NN + n) * 15 + f] : 0.f;
    }
    __syncthreads();
    if (t < 256) gemm_act(Xi, 16, 8, g_W1p, b1, Ps, t);
    __syncthreads();
    if (t < 256) gemm_act(Ps, NPAD, 64, g_W2p, b2, Xs, t);

    // ---------------- 3 x EdgeConv ----------------
    for (int layer = 0; layer < 3; layer++) {
        __syncthreads();  // Xs ready; Ap free
        // convert Xs -> packed bf16 hi/lo planes (16 cols/thread) + squared norms
        {
            int n = t >> 3, cb = (t & 7) * 16;
            unsigned* xph = Xp + n * XPS + cb / 2;
            unsigned* xpl = xph + 64 * XPS;
            const float* src = Xs + n * NPAD + cb;
#pragma unroll
            for (int i = 0; i < 4; i++) {
                float4 v = *(const float4*)(src + i * 4);
                __nv_bfloat162 h01 = __floats2bfloat162_rn(v.x, v.y);
                __nv_bfloat162 h23 = __floats2bfloat162_rn(v.z, v.w);
                float2 hf01 = __bfloat1622float2(h01);
                float2 hf23 = __bfloat1622float2(h23);
                __nv_bfloat162 l01 = __floats2bfloat162_rn(v.x - hf01.x, v.y - hf01.y);
                __nv_bfloat162 l23 = __floats2bfloat162_rn(v.z - hf23.x, v.w - hf23.y);
                xph[i * 2]     = *reinterpret_cast<unsigned*>(&h01);
                xph[i * 2 + 1] = *reinterpret_cast<unsigned*>(&h23);
                xpl[i * 2]     = *reinterpret_cast<unsigned*>(&l01);
                xpl[i * 2 + 1] = *reinterpret_cast<unsigned*>(&l23);
            }
        }
        if (t < NN) {
            u64 a0 = 0, a1 = 0;
#pragma unroll 8
            for (int k4 = 0; k4 < 32; k4++) {
                ulonglong2 v = *(const ulonglong2*)(Xs + t * NPAD + k4 * 4);
                fma2(a0, v.x, v.x);
                fma2(a1, v.y, v.y);
            }
            sq[t] = hadd(a0) + hadd(a1);
        }
        __syncthreads();
        // merged MMA phase: dist (keys -> Xs window), then edge accumulate,
        // internal barrier (inside gemm_edge_mma), then edge writes Ap/Ps.
        dist_mma(Xp, sq, dsu, t);
        gemm_edge_mma(Xp, Ap, Ps, t);
        __syncthreads();
        // exact top-K by rank counting (8 j's per thread)
        {
            int i = t >> 3, jb = (t & 7) * 8;
            unsigned kj[8];
#pragma unroll
            for (int jj = 0; jj < 8; jj++) kj[jj] = dsu[i * DPAD + jb + jj];
            int rk[8];
#pragma unroll
            for (int jj = 0; jj < 8; jj++) rk[jj] = 0;
#pragma unroll 8
            for (int m = 0; m < 64; m++) {
                unsigned km = dsu[i * DPAD + m];
#pragma unroll
                for (int jj = 0; jj < 8; jj++) rk[jj] += (km < kj[jj]) ? 1 : 0;
            }
#pragma unroll
            for (int jj = 0; jj < 8; jj++)
                if (rk[jj] < KNN) idxs[i * KNN + rk[jj]] = jb + jj;
        }
        __syncthreads();
        // gather-max: warp-per-node, 16 warps x 4 nodes; writes Xs over dead keys
        {
            int w = t >> 5, lane = t & 31;
#pragma unroll
            for (int p = 0; p < 2; p++) {
                int n0 = w * 4 + 2 * p;
                int n1 = n0 + 1;
                float4 m0 = make_float4(-3.4e38f, -3.4e38f, -3.4e38f, -3.4e38f);
                float4 m1 = m0;
#pragma unroll 6
                for (int k = 0; k < KNN; k++) {
                    int i0 = idxs[n0 * KNN + k];
                    int i1 = idxs[n1 * KNN + k];
                    float4 v0 = *(const float4*)(Ps + i0 * NPAD + lane * 4);
                    float4 v1 = *(const float4*)(Ps + i1 * NPAD + lane * 4);
                    m0.x = fmaxf(m0.x, v0.x); m0.y = fmaxf(m0.y, v0.y);
                    m0.z = fmaxf(m0.z, v0.z); m0.w = fmaxf(m0.w, v0.w);
                    m1.x = fmaxf(m1.x, v1.x); m1.y = fmaxf(m1.y, v1.y);
                    m1.z = fmaxf(m1.z, v1.z); m1.w = fmaxf(m1.w, v1.w);
                }
                float4 a0 = *(const float4*)(Ap + n0 * NPAD + lane * 4);
                float4 a1 = *(const float4*)(Ap + n1 * NPAD + lane * 4);
                float4 bcv = *(const float4*)(bc + lane * 4);
                float4 r0, r1;
                r0.x = elu1(m0.x + a0.x + bcv.x);
                r0.y = elu1(m0.y + a0.y + bcv.y);
                r0.z = elu1(m0.z + a0.z + bcv.z);
                r0.w = elu1(m0.w + a0.w + bcv.w);
                r1.x = elu1(m1.x + a1.x + bcv.x);
                r1.y = elu1(m1.y + a1.y + bcv.y);
                r1.z = elu1(m1.z + a1.z + bcv.z);
                r1.w = elu1(m1.w + a1.w + bcv.w);
                *(float4*)(Xs + n0 * NPAD + lane * 4) = r0;
                *(float4*)(Xs + n1 * NPAD + lane * 4) = r1;
            }
        }
    }
    __syncthreads();

    // ---------------- pool + head MLP ----------------
    float* pooled = hd;        // 128
    float* o1 = hd + 128;      // 64
    float* o2 = hd + 192;      // 32
    float* o3 = hd + 224;      // 32
    if (t < 128) {
        float s = 0.f;
#pragma unroll 8
        for (int n = 0; n < NN; n++) s += Xs[n * NPAD + t];
        pooled[t] = s;
    }
    __syncthreads();
    if (t < 64) {
        float s = bo1[t];
        for (int k = 0; k < 128; k++) s = fmaf(pooled[k], Wo1[k * 64 + t], s);
        o1[t] = elu1(s);
    }
    __syncthreads();
    if (t < 32) {
        float s = bo2[t];
        for (int k = 0; k < 64; k++) s = fmaf(o1[k], Wo2[k * 32 + t], s);
        o2[t] = elu1(s);
    }
    __syncthreads();
    if (t < 32) {
        float s = bo3[t];
        for (int k = 0; k < 32; k++) s = fmaf(o2[k], Wo3[k * 32 + t], s);
        o3[t] = elu1(s);
    }
    __syncthreads();
    if (t < 8) {
        float s = bo4[t];
        for (int k = 0; k < 32; k++) s = fmaf(o3[k], Wo4[k * 8 + t], s);
        out[g * 8 + t] = s;
    }
    if (write_batch) {
        for (int l = t; l < NN; l += NT)
            out[NG * 8 + g * NN + l] = (float)g;
    }
}

static const int SMEM_BYTES = SMEM_FLOATS * 4;  // 108800

extern "C" void kernel_launch(void* const* d_in, const int* in_sizes, int n_in,
                              void* d_out, int out_size) {
    const float* x_pf = (const float*)d_in[0];
    // d_in[1] = batch_pf (implicit: node n belongs to graph n/64)
    const float* W1  = (const float*)d_in[2];
    const float* b1  = (const float*)d_in[3];
    const float* W2  = (const float*)d_in[4];
    const float* b2  = (const float*)d_in[5];
    const float* Wc  = (const float*)d_in[6];
    const float* bc  = (const float*)d_in[7];
    const float* Wo1 = (const float*)d_in[8];
    const float* bo1 = (const float*)d_in[9];
    const float* Wo2 = (const float*)d_in[10];
    const float* bo2 = (const float*)d_in[11];
    const float* Wo3 = (const float*)d_in[12];
    const float* bo3 = (const float*)d_in[13];
    const float* Wo4 = (const float*)d_in[14];
    const float* bo4 = (const float*)d_in[15];

    cudaFuncSetAttribute(net_kernel, cudaFuncAttributeMaxDynamicSharedMemorySize, SMEM_BYTES);

    prep_kernel<<<164, 256>>>(Wc, W1, W2);

    int write_batch = (out_size >= NG * 8 + NG * NN) ? 1 : 0;
    net_kernel<<<NG, NT, SMEM_BYTES>>>(x_pf, b1, b2, bc,
                                       Wo1, bo1, Wo2, bo2, Wo3, bo3, Wo4, bo4,
                                       (float*)d_out, write_batch);
}

// round 11
// speedup vs baseline: 2.1045x; 2.1045x over previous
#include <cuda_runtime.h>
#include <cuda_bf16.h>

typedef unsigned long long u64;

#define NG   256
#define NN   64
#define KNN  24
#define HID  128
#define NPAD 132   // float stride for fp32 64x128 tiles
#define DPAD 68    // uint stride for 64x64 key matrix
#define XPS  66    // u32 stride for packed bf16 planes
#define NT   256   // threads per CTA

// fragment-ordered bf16 edge weights: [part 2][split 2][kstep 8][ntile 16][lane 32][2] u32
__device__ __align__(16) unsigned g_Wfe[2 * 2 * 8 * 16 * 32 * 2];
// fragment-ordered bf16 W2: [split 2][kstep 8][ntile 16][lane 32][2] u32
__device__ __align__(16) unsigned g_W2f[2 * 8 * 16 * 32 * 2];
// k-pair-packed fp32 W1 (K=15 padded to 16)
__device__ u64 g_W1p[8 * 128];

__device__ __forceinline__ void fma2(u64& d, u64 a, u64 b) {
    asm("fma.rn.f32x2 %0, %1, %2, %0;" : "+l"(d) : "l"(a), "l"(b));
}
__device__ __forceinline__ float2 upk(u64 v) {
    float2 f; asm("mov.b64 {%0, %1}, %2;" : "=f"(f.x), "=f"(f.y) : "l"(v)); return f;
}
__device__ __forceinline__ u64 pk(float lo, float hi) {
    u64 r; asm("mov.b64 %0, {%1, %2};" : "=l"(r) : "f"(lo), "f"(hi)); return r;
}
__device__ __forceinline__ float hadd(u64 v) {
    float2 f = upk(v); return f.x + f.y;
}
__device__ __forceinline__ float elu1(float x) {
    return x > 0.f ? x : (__expf(x) - 1.f);
}
__device__ __forceinline__ unsigned fkey(float d) {
    unsigned u = __float_as_uint(d);
    return ((int)u < 0) ? ~u : (u | 0x80000000u);
}
__device__ __forceinline__ unsigned pkbf2(float a, float b) {
    __nv_bfloat162 h = __floats2bfloat162_rn(a, b);
    return *reinterpret_cast<unsigned*>(&h);
}
__device__ __forceinline__ float bf16f(float v) {
    return __bfloat162float(__float2bfloat16_rn(v));
}

__device__ __forceinline__ void mma_bf16(float* c, const unsigned* a, unsigned b0, unsigned b1) {
    asm volatile("mma.sync.aligned.m16n8k16.row.col.f32.bf16.bf16.f32 "
        "{%0,%1,%2,%3}, {%4,%5,%6,%7}, {%8,%9}, {%0,%1,%2,%3};\n"
        : "+f"(c[0]), "+f"(c[1]), "+f"(c[2]), "+f"(c[3])
        : "r"(a[0]), "r"(a[1]), "r"(a[2]), "r"(a[3]), "r"(b0), "r"(b1));
}

// Wcat(k, cc): cc<128 -> Wc_top - Wc_bot ('a' weights); else Wc_bot ('p' weights)
__device__ __forceinline__ float wcat(const float* Wc, int k, int cc) {
    if (cc < HID) return Wc[k * HID + cc] - Wc[(HID + k) * HID + cc];
    return Wc[(HID + k) * HID + (cc - HID)];
}

__global__ void prep_kernel(const float* __restrict__ Wc,
                            const float* __restrict__ W1,
                            const float* __restrict__ W2) {
    int i = blockIdx.x * blockDim.x + threadIdx.x;
    if (i < 32768) {
        int r = i & 1, L = (i >> 1) & 31, nt = (i >> 6) & 15;
        int ks = (i >> 10) & 7, sp = (i >> 13) & 1, part = (i >> 14) & 1;
        int c  = nt * 8 + (L >> 2);
        int k0 = ks * 16 + (L & 3) * 2 + r * 8;
        int cc = part * HID + c;
        float v0 = wcat(Wc, k0, cc);
        float v1 = wcat(Wc, k0 + 1, cc);
        unsigned u;
        if (sp == 0) u = pkbf2(v0, v1);
        else         u = pkbf2(v0 - bf16f(v0), v1 - bf16f(v1));
        g_Wfe[i] = u;
    }
    int j = i - 32768;
    if (j >= 0 && j < 16384) {
        int r = j & 1, L = (j >> 1) & 31, nt = (j >> 6) & 15;
        int ks = (j >> 10) & 7, sp = (j >> 13) & 1;
        int c  = nt * 8 + (L >> 2);
        int k0 = ks * 16 + (L & 3) * 2 + r * 8;
        float v0 = W2[k0 * HID + c];
        float v1 = W2[(k0 + 1) * HID + c];
        unsigned u;
        if (sp == 0) u = pkbf2(v0, v1);
        else         u = pkbf2(v0 - bf16f(v0), v1 - bf16f(v1));
        g_W2f[j] = u;
    }
    int l = i - 32768 - 16384;
    if (l >= 0 && l < 8 * 128) {
        int kp = l >> 7, c = l & 127;
        float lo = W1[(2 * kp) * HID + c];
        float hi = (2 * kp + 1 < 15) ? W1[(2 * kp + 1) * HID + c] : 0.f;
        g_W1p[l] = pk(lo, hi);
    }
}

// Out[64x128] = elu( Xin[64 x 2*KP] @ W + bias ). 256 threads, 8 rows x 4 cols per thread.
__device__ __forceinline__ void gemm_act(const float* __restrict__ Xin, int xs, int KP,
                                         const u64* __restrict__ Wp,
                                         const float* __restrict__ bias,
                                         float* __restrict__ Out, int t) {
    int n0 = (t >> 5) * 8;
    int c0 = (t & 31) * 4;
    u64 acc[8][4];
#pragma unroll
    for (int i = 0; i < 8; i++) { acc[i][0] = 0; acc[i][1] = 0; acc[i][2] = 0; acc[i][3] = 0; }
#pragma unroll 4
    for (int kp = 0; kp < KP; kp++) {
        const u64* wr = Wp + kp * 128 + c0;
        ulonglong2 wa = *(const ulonglong2*)(wr);
        ulonglong2 wb = *(const ulonglong2*)(wr + 2);
        u64 xv[8];
#pragma unroll
        for (int i = 0; i < 8; i++) xv[i] = *(const u64*)(Xin + (n0 + i) * xs + 2 * kp);
#pragma unroll
        for (int i = 0; i < 8; i++) {
            fma2(acc[i][0], xv[i], wa.x);
            fma2(acc[i][1], xv[i], wa.y);
            fma2(acc[i][2], xv[i], wb.x);
            fma2(acc[i][3], xv[i], wb.y);
        }
    }
    float4 b = *(const float4*)(bias + c0);
#pragma unroll
    for (int i = 0; i < 8; i++) {
        float4 r;
        r.x = elu1(hadd(acc[i][0]) + b.x);
        r.y = elu1(hadd(acc[i][1]) + b.y);
        r.z = elu1(hadd(acc[i][2]) + b.z);
        r.w = elu1(hadd(acc[i][3]) + b.w);
        *(float4*)(Out + (n0 + i) * NPAD + c0) = r;
    }
}

// Convert fp32 tile (stride NPAD) -> packed bf16 hi/lo planes in Xp. 256 threads, 32 cols each.
__device__ __forceinline__ void convert_planes(const float* __restrict__ src0,
                                               unsigned* __restrict__ Xp, int t) {
    int n = t >> 2, cb = (t & 3) * 32;
    unsigned* xph = Xp + n * XPS + cb / 2;
    unsigned* xpl = xph + 64 * XPS;
    const float* src = src0 + n * NPAD + cb;
#pragma unroll
    for (int i = 0; i < 8; i++) {
        float4 v = *(const float4*)(src + i * 4);
        __nv_bfloat162 h01 = __floats2bfloat162_rn(v.x, v.y);
        __nv_bfloat162 h23 = __floats2bfloat162_rn(v.z, v.w);
        float2 hf01 = __bfloat1622float2(h01);
        float2 hf23 = __bfloat1622float2(h23);
        __nv_bfloat162 l01 = __floats2bfloat162_rn(v.x - hf01.x, v.y - hf01.y);
        __nv_bfloat162 l23 = __floats2bfloat162_rn(v.z - hf23.x, v.w - hf23.y);
        xph[i * 2]     = *reinterpret_cast<unsigned*>(&h01);
        xph[i * 2 + 1] = *reinterpret_cast<unsigned*>(&h23);
        xpl[i * 2]     = *reinterpret_cast<unsigned*>(&l01);
        xpl[i * 2 + 1] = *reinterpret_cast<unsigned*>(&l23);
    }
}

// Stage-1 W2 on tensor cores (3-term bf16 split): Out = elu(h1 @ W2 + b2).
// 8 warps: rows 16*(w&3), ntile half (w>>2)*8. 32 acc regs.
__device__ __forceinline__ void w2_mma(const unsigned* __restrict__ Xp,
                                       const float* __restrict__ b2,
                                       float* __restrict__ Out, int t) {
    int w = t >> 5, L = t & 31;
    int m0 = (w & 3) * 16;
    int nt0 = (w >> 2) * 8;
    const unsigned* xh = Xp + (m0 + (L >> 2)) * XPS + (L & 3);
    const unsigned* xl = xh + 64 * XPS;
    float acc[8][4];
#pragma unroll
    for (int q = 0; q < 8; q++) {
        acc[q][0] = 0.f; acc[q][1] = 0.f; acc[q][2] = 0.f; acc[q][3] = 0.f;
    }
    const unsigned* wb = g_W2f + L * 2;
#pragma unroll
    for (int ks = 0; ks < 8; ks++) {
        unsigned ah[4], al[4];
        ah[0] = xh[ks * 8];         ah[1] = xh[8 * XPS + ks * 8];
        ah[2] = xh[ks * 8 + 4];     ah[3] = xh[8 * XPS + ks * 8 + 4];
        al[0] = xl[ks * 8];         al[1] = xl[8 * XPS + ks * 8];
        al[2] = xl[ks * 8 + 4];     al[3] = xl[8 * XPS + ks * 8 + 4];
#pragma unroll
        for (int q = 0; q < 8; q++) {
            const unsigned* wp = wb + (ks * 16 + nt0 + q) * 64;
            uint2 bh = *(const uint2*)(wp);
            uint2 bl = *(const uint2*)(wp + 8192);
            mma_bf16(acc[q], ah, bh.x, bh.y);
            mma_bf16(acc[q], ah, bl.x, bl.y);
            mma_bf16(acc[q], al, bh.x, bh.y);
        }
    }
    int row = m0 + (L >> 2);
    int col0 = (L & 3) * 2;
#pragma unroll
    for (int q = 0; q < 8; q++) {
        int c = (nt0 + q) * 8 + col0;
        Out[row * NPAD + c]           = elu1(acc[q][0] + b2[c]);
        Out[row * NPAD + c + 1]       = elu1(acc[q][1] + b2[c + 1]);
        Out[(row + 8) * NPAD + c]     = elu1(acc[q][2] + b2[c]);
        Out[(row + 8) * NPAD + c + 1] = elu1(acc[q][3] + b2[c + 1]);
    }
}

// Distance Gram on tensor cores (4-term bf16 split). 8 warps: rows 16*(w&3), cols 32*(w>>2).
__device__ __forceinline__ void dist_mma(const unsigned* __restrict__ Xp,
                                         const float* __restrict__ sq,
                                         unsigned* __restrict__ dsu, int t) {
    int w = t >> 5, L = t & 31;
    int m0 = (w & 3) * 16;
    int nbase = (w >> 2) * 32;
    const unsigned* xh = Xp + (m0 + (L >> 2)) * XPS + (L & 3);
    const unsigned* xl = xh + 64 * XPS;
    const unsigned* bbase = Xp + (nbase + (L >> 2)) * XPS + (L & 3);
    float acc[4][4];
#pragma unroll
    for (int nt = 0; nt < 4; nt++) {
        acc[nt][0] = 0.f; acc[nt][1] = 0.f; acc[nt][2] = 0.f; acc[nt][3] = 0.f;
    }
#pragma unroll
    for (int ks = 0; ks < 8; ks++) {
        unsigned ah[4], al[4];
        ah[0] = xh[ks * 8];         ah[1] = xh[8 * XPS + ks * 8];
        ah[2] = xh[ks * 8 + 4];     ah[3] = xh[8 * XPS + ks * 8 + 4];
        al[0] = xl[ks * 8];         al[1] = xl[8 * XPS + ks * 8];
        al[2] = xl[ks * 8 + 4];     al[3] = xl[8 * XPS + ks * 8 + 4];
#pragma unroll
        for (int nt = 0; nt < 4; nt++) {
            const unsigned* bh = bbase + nt * 8 * XPS + ks * 8;
            const unsigned* bl = bh + 64 * XPS;
            unsigned bh0 = bh[0], bh1 = bh[4];
            unsigned bl0 = bl[0], bl1 = bl[4];
            mma_bf16(acc[nt], ah, bh0, bh1);
            mma_bf16(acc[nt], ah, bl0, bl1);
            mma_bf16(acc[nt], al, bh0, bh1);
            mma_bf16(acc[nt], al, bl0, bl1);
        }
    }
    int r0 = m0 + (L >> 2);
    float si0 = sq[r0], si1 = sq[r0 + 8];
#pragma unroll
    for (int nt = 0; nt < 4; nt++) {
        int c0 = nbase + nt * 8 + (L & 3) * 2;
        float sj0 = sq[c0], sj1 = sq[c0 + 1];
        dsu[r0 * DPAD + c0]           = fkey(si0 + sj0 - 2.f * acc[nt][0]);
        dsu[r0 * DPAD + c0 + 1]       = fkey(si0 + sj1 - 2.f * acc[nt][1]);
        dsu[(r0 + 8) * DPAD + c0]     = fkey(si1 + sj0 - 2.f * acc[nt][2]);
        dsu[(r0 + 8) * DPAD + c0 + 1] = fkey(si1 + sj1 - 2.f * acc[nt][3]);
    }
}

// Edge gemm on tensor cores (3-term bf16 split). 8 warps: part=w>>2, rows 16*(w&3), 16 ntiles.
// Internal barrier before epilogue (covers dist's + edge's Xp reads).
__device__ void gemm_edge_mma(const unsigned* __restrict__ Xp,
                              float* __restrict__ Aout,
                              float* __restrict__ Pout, int t) {
    int w = t >> 5, L = t & 31;
    int part = w >> 2;
    int m0 = (w & 3) * 16;
    const unsigned* xh = Xp + (m0 + (L >> 2)) * XPS + (L & 3);
    const unsigned* xl = xh + 64 * XPS;
    float acc[16][4];
#pragma unroll
    for (int nt = 0; nt < 16; nt++) {
        acc[nt][0] = 0.f; acc[nt][1] = 0.f; acc[nt][2] = 0.f; acc[nt][3] = 0.f;
    }
    const unsigned* wb = g_Wfe + part * 16384 + L * 2;
#pragma unroll
    for (int ks = 0; ks < 8; ks++) {
        unsigned ah[4], al[4];
        ah[0] = xh[ks * 8];         ah[1] = xh[8 * XPS + ks * 8];
        ah[2] = xh[ks * 8 + 4];     ah[3] = xh[8 * XPS + ks * 8 + 4];
        al[0] = xl[ks * 8];         al[1] = xl[8 * XPS + ks * 8];
        al[2] = xl[ks * 8 + 4];     al[3] = xl[8 * XPS + ks * 8 + 4];
#pragma unroll
        for (int nt = 0; nt < 16; nt++) {
            const unsigned* wp = wb + (ks * 16 + nt) * 64;
            uint2 bh = *(const uint2*)(wp);
            uint2 bl = *(const uint2*)(wp + 8192);
            mma_bf16(acc[nt], ah, bh.x, bh.y);   // hi*hi
            mma_bf16(acc[nt], ah, bl.x, bl.y);   // hi*lo
            mma_bf16(acc[nt], al, bh.x, bh.y);   // lo*hi
        }
    }
    __syncthreads();   // all Xp reads (dist + edge) done; safe to overwrite Ap and Ps
    float* dst = part ? Pout : Aout;
    int row = m0 + (L >> 2);
    int col0 = (L & 3) * 2;
#pragma unroll
    for (int nt = 0; nt < 16; nt++) {
        *(float2*)(dst + row * NPAD + nt * 8 + col0)       = make_float2(acc[nt][0], acc[nt][1]);
        *(float2*)(dst + (row + 8) * NPAD + nt * 8 + col0) = make_float2(acc[nt][2], acc[nt][3]);
    }
}

// smem layout (floats)
#define OFF_XS  0                      // Xs fp32 features / distance keys
#define OFF_AP  (NN * NPAD)            // Ap: 'a' fp32 / bf16 Xp planes / Xi scratch
#define OFF_PS  (2 * NN * NPAD)        // Ps: 'p' fp32 / h1 scratch
#define OFF_IDX (3 * NN * NPAD)
#define SMEM_FLOATS (OFF_IDX + NN * KNN + NN + 256)

__global__ __launch_bounds__(NT, 2)
void net_kernel(const float* __restrict__ x_pf,
                const float* __restrict__ b1, const float* __restrict__ b2,
                const float* __restrict__ bc,
                const float* __restrict__ Wo1, const float* __restrict__ bo1,
                const float* __restrict__ Wo2, const float* __restrict__ bo2,
                const float* __restrict__ Wo3, const float* __restrict__ bo3,
                const float* __restrict__ Wo4, const float* __restrict__ bo4,
                float* __restrict__ out, int write_batch) {
    extern __shared__ __align__(16) float sm[];
    float* Xs = sm + OFF_XS;
    float* Ap = sm + OFF_AP;
    float* Ps = sm + OFF_PS;
    int*   idxs = (int*)(sm + OFF_IDX);
    float* sq = sm + OFF_IDX + NN * KNN;
    float* hd = sq + NN;
    unsigned* dsu = (unsigned*)Xs;     // distance keys in Xs window (fp32 X dead after convert)
    unsigned* Xp  = (unsigned*)Ap;     // bf16 planes in Ap window

    int g = blockIdx.x;
    int t = threadIdx.x;

    // ---------------- Stage 1: h = elu(elu(x@W1+b1)@W2+b2) ----------------
    float* Xi = Ap;  // temp [64][16], col 15 zeroed
    for (int i = t; i < NN * 16; i += NT) {
        int n = i >> 4, f = i & 15;
        Xi[i] = (f < 15) ? x_pf[(g * NN + n) * 15 + f] : 0.f;
    }
    __syncthreads();
    gemm_act(Xi, 16, 8, g_W1p, b1, Ps, t);   // h1 (elu) -> Ps
    __syncthreads();
    convert_planes(Ps, Xp, t);               // h1 -> bf16 planes (Ap window; Xi dead)
    __syncthreads();
    w2_mma(Xp, b2, Xs, t);                   // h (elu) -> Xs

    // ---------------- 3 x EdgeConv ----------------
    for (int layer = 0; layer < 3; layer++) {
        __syncthreads();  // Xs ready; Ap free
        convert_planes(Xs, Xp, t);
        if (t < NN) {
            u64 a0 = 0, a1 = 0;
#pragma unroll 8
            for (int k4 = 0; k4 < 32; k4++) {
                ulonglong2 v = *(const ulonglong2*)(Xs + t * NPAD + k4 * 4);
                fma2(a0, v.x, v.x);
                fma2(a1, v.y, v.y);
            }
            sq[t] = hadd(a0) + hadd(a1);
        }
        __syncthreads();
        // merged MMA phase: dist writes keys over dead Xs, edge accumulates,
        // internal barrier (inside gemm_edge_mma), then edge writes Ap/Ps.
        dist_mma(Xp, sq, dsu, t);
        gemm_edge_mma(Xp, Ap, Ps, t);
        __syncthreads();
        // exact top-K by rank counting
        {
            int i = t >> 2, jb = (t & 3) * 16;
            unsigned kj[16];
#pragma unroll
            for (int jj = 0; jj < 16; jj++) kj[jj] = dsu[i * DPAD + jb + jj];
            int rk[16];
#pragma unroll
            for (int jj = 0; jj < 16; jj++) rk[jj] = 0;
#pragma unroll 4
            for (int m = 0; m < 64; m++) {
                unsigned km = dsu[i * DPAD + m];
#pragma unroll
                for (int jj = 0; jj < 16; jj++) rk[jj] += (km < kj[jj]) ? 1 : 0;
            }
#pragma unroll
            for (int jj = 0; jj < 16; jj++)
                if (rk[jj] < KNN) idxs[i * KNN + rk[jj]] = jb + jj;
        }
        __syncthreads();
        // gather-max: warp-per-node, full contiguous rows; writes Xs over dead keys
        {
            int w = t >> 5, lane = t & 31;
#pragma unroll
            for (int p = 0; p < 4; p++) {
                int n0 = w * 8 + 2 * p;
                int n1 = n0 + 1;
                float4 m0 = make_float4(-3.4e38f, -3.4e38f, -3.4e38f, -3.4e38f);
                float4 m1 = m0;
#pragma unroll 6
                for (int k = 0; k < KNN; k++) {
                    int i0 = idxs[n0 * KNN + k];
                    int i1 = idxs[n1 * KNN + k];
                    float4 v0 = *(const float4*)(Ps + i0 * NPAD + lane * 4);
                    float4 v1 = *(const float4*)(Ps + i1 * NPAD + lane * 4);
                    m0.x = fmaxf(m0.x, v0.x); m0.y = fmaxf(m0.y, v0.y);
                    m0.z = fmaxf(m0.z, v0.z); m0.w = fmaxf(m0.w, v0.w);
                    m1.x = fmaxf(m1.x, v1.x); m1.y = fmaxf(m1.y, v1.y);
                    m1.z = fmaxf(m1.z, v1.z); m1.w = fmaxf(m1.w, v1.w);
                }
                float4 a0 = *(const float4*)(Ap + n0 * NPAD + lane * 4);
                float4 a1 = *(const float4*)(Ap + n1 * NPAD + lane * 4);
                float4 bcv = *(const float4*)(bc + lane * 4);
                float4 r0, r1;
                r0.x = elu1(m0.x + a0.x + bcv.x);
                r0.y = elu1(m0.y + a0.y + bcv.y);
                r0.z = elu1(m0.z + a0.z + bcv.z);
                r0.w = elu1(m0.w + a0.w + bcv.w);
                r1.x = elu1(m1.x + a1.x + bcv.x);
                r1.y = elu1(m1.y + a1.y + bcv.y);
                r1.z = elu1(m1.z + a1.z + bcv.z);
                r1.w = elu1(m1.w + a1.w + bcv.w);
                *(float4*)(Xs + n0 * NPAD + lane * 4) = r0;
                *(float4*)(Xs + n1 * NPAD + lane * 4) = r1;
            }
        }
    }
    __syncthreads();

    // ---------------- pool + head MLP ----------------
    float* pooled = hd;        // 128
    float* o1 = hd + 128;      // 64
    float* o2 = hd + 192;      // 32
    float* o3 = hd + 224;      // 32
    if (t < 128) {
        float s = 0.f;
#pragma unroll 8
        for (int n = 0; n < NN; n++) s += Xs[n * NPAD + t];
        pooled[t] = s;
    }
    __syncthreads();
    if (t < 64) {
        float s = bo1[t];
        for (int k = 0; k < 128; k++) s = fmaf(pooled[k], Wo1[k * 64 + t], s);
        o1[t] = elu1(s);
    }
    __syncthreads();
    if (t < 32) {
        float s = bo2[t];
        for (int k = 0; k < 64; k++) s = fmaf(o1[k], Wo2[k * 32 + t], s);
        o2[t] = elu1(s);
    }
    __syncthreads();
    if (t < 32) {
        float s = bo3[t];
        for (int k = 0; k < 32; k++) s = fmaf(o2[k], Wo3[k * 32 + t], s);
        o3[t] = elu1(s);
    }
    __syncthreads();
    if (t < 8) {
        float s = bo4[t];
        for (int k = 0; k < 32; k++) s = fmaf(o3[k], Wo4[k * 8 + t], s);
        out[g * 8 + t] = s;
    }
    if (write_batch) {
        for (int l = t; l < NN; l += NT)
            out[NG * 8 + g * NN + l] = (float)g;
    }
}

static const int SMEM_BYTES = SMEM_FLOATS * 4;  // 108800

extern "C" void kernel_launch(void* const* d_in, const int* in_sizes, int n_in,
                              void* d_out, int out_size) {
    const float* x_pf = (const float*)d_in[0];
    // d_in[1] = batch_pf (implicit: node n belongs to graph n/64)
    const float* W1  = (const float*)d_in[2];
    const float* b1  = (const float*)d_in[3];
    const float* W2  = (const float*)d_in[4];
    const float* b2  = (const float*)d_in[5];
    const float* Wc  = (const float*)d_in[6];
    const float* bc  = (const float*)d_in[7];
    const float* Wo1 = (const float*)d_in[8];
    const float* bo1 = (const float*)d_in[9];
    const float* Wo2 = (const float*)d_in[10];
    const float* bo2 = (const float*)d_in[11];
    const float* Wo3 = (const float*)d_in[12];
    const float* bo3 = (const float*)d_in[13];
    const float* Wo4 = (const float*)d_in[14];
    const float* bo4 = (const float*)d_in[15];

    cudaFuncSetAttribute(net_kernel, cudaFuncAttributeMaxDynamicSharedMemorySize, SMEM_BYTES);

    prep_kernel<<<196, 256>>>(Wc, W1, W2);

    int write_batch = (out_size >= NG * 8 + NG * NN) ? 1 : 0;
    net_kernel<<<NG, NT, SMEM_BYTES>>>(x_pf, b1, b2, bc,
                                       Wo1, bo1, Wo2, bo2, Wo3, bo3, Wo4, bo4,
                                       (float*)d_out, write_batch);
}

// round 12
// speedup vs baseline: 2.1993x; 1.0451x over previous
#include <cuda_runtime.h>
#include <cuda_bf16.h>

typedef unsigned long long u64;

#define NG   256
#define NN   64
#define KNN  24
#define HID  128
#define NPAD 132   // float stride for fp32 64x128 tiles
#define DPAD 68    // float stride for 64x64 distance matrix
#define XPS  66    // u32 stride for packed bf16 planes
#define NT   256   // threads per CTA

// fragment-ordered bf16 edge weights: [part 2][split 2][kstep 8][ntile 16][lane 32][2] u32
__device__ __align__(16) unsigned g_Wfe[2 * 2 * 8 * 16 * 32 * 2];
// fragment-ordered bf16 W2: [split 2][kstep 8][ntile 16][lane 32][2] u32
__device__ __align__(16) unsigned g_W2f[2 * 8 * 16 * 32 * 2];
// k-pair-packed fp32 W1 (K=15 padded to 16)
__device__ u64 g_W1p[8 * 128];

__device__ __forceinline__ void fma2(u64& d, u64 a, u64 b) {
    asm("fma.rn.f32x2 %0, %1, %2, %0;" : "+l"(d) : "l"(a), "l"(b));
}
__device__ __forceinline__ float2 upk(u64 v) {
    float2 f; asm("mov.b64 {%0, %1}, %2;" : "=f"(f.x), "=f"(f.y) : "l"(v)); return f;
}
__device__ __forceinline__ u64 pk(float lo, float hi) {
    u64 r; asm("mov.b64 %0, {%1, %2};" : "=l"(r) : "f"(lo), "f"(hi)); return r;
}
__device__ __forceinline__ float hadd(u64 v) {
    float2 f = upk(v); return f.x + f.y;
}
__device__ __forceinline__ float elu1(float x) {
    return x > 0.f ? x : (__expf(x) - 1.f);
}
__device__ __forceinline__ unsigned pkbf2(float a, float b) {
    __nv_bfloat162 h = __floats2bfloat162_rn(a, b);
    return *reinterpret_cast<unsigned*>(&h);
}
__device__ __forceinline__ float bf16f(float v) {
    return __bfloat162float(__float2bfloat16_rn(v));
}

__device__ __forceinline__ void mma_bf16(float* c, const unsigned* a, unsigned b0, unsigned b1) {
    asm volatile("mma.sync.aligned.m16n8k16.row.col.f32.bf16.bf16.f32 "
        "{%0,%1,%2,%3}, {%4,%5,%6,%7}, {%8,%9}, {%0,%1,%2,%3};\n"
        : "+f"(c[0]), "+f"(c[1]), "+f"(c[2]), "+f"(c[3])
        : "r"(a[0]), "r"(a[1]), "r"(a[2]), "r"(a[3]), "r"(b0), "r"(b1));
}

// Wcat(k, cc): cc<128 -> Wc_top - Wc_bot ('a' weights); else Wc_bot ('p' weights)
__device__ __forceinline__ float wcat(const float* Wc, int k, int cc) {
    if (cc < HID) return Wc[k * HID + cc] - Wc[(HID + k) * HID + cc];
    return Wc[(HID + k) * HID + (cc - HID)];
}

__global__ void prep_kernel(const float* __restrict__ Wc,
                            const float* __restrict__ W1,
                            const float* __restrict__ W2) {
    int i = blockIdx.x * blockDim.x + threadIdx.x;
    if (i < 32768) {
        int r = i & 1, L = (i >> 1) & 31, nt = (i >> 6) & 15;
        int ks = (i >> 10) & 7, sp = (i >> 13) & 1, part = (i >> 14) & 1;
        int c  = nt * 8 + (L >> 2);
        int k0 = ks * 16 + (L & 3) * 2 + r * 8;
        int cc = part * HID + c;
        float v0 = wcat(Wc, k0, cc);
        float v1 = wcat(Wc, k0 + 1, cc);
        unsigned u;
        if (sp == 0) u = pkbf2(v0, v1);
        else         u = pkbf2(v0 - bf16f(v0), v1 - bf16f(v1));
        g_Wfe[i] = u;
    }
    int j = i - 32768;
    if (j >= 0 && j < 16384) {
        int r = j & 1, L = (j >> 1) & 31, nt = (j >> 6) & 15;
        int ks = (j >> 10) & 7, sp = (j >> 13) & 1;
        int c  = nt * 8 + (L >> 2);
        int k0 = ks * 16 + (L & 3) * 2 + r * 8;
        float v0 = W2[k0 * HID + c];
        float v1 = W2[(k0 + 1) * HID + c];
        unsigned u;
        if (sp == 0) u = pkbf2(v0, v1);
        else         u = pkbf2(v0 - bf16f(v0), v1 - bf16f(v1));
        g_W2f[j] = u;
    }
    int l = i - 32768 - 16384;
    if (l >= 0 && l < 8 * 128) {
        int kp = l >> 7, c = l & 127;
        float lo = W1[(2 * kp) * HID + c];
        float hi = (2 * kp + 1 < 15) ? W1[(2 * kp + 1) * HID + c] : 0.f;
        g_W1p[l] = pk(lo, hi);
    }
}

// Out[64x128] = elu( Xin[64 x 2*KP] @ W + bias ). 256 threads, 8 rows x 4 cols per thread.
__device__ __forceinline__ void gemm_act(const float* __restrict__ Xin, int xs, int KP,
                                         const u64* __restrict__ Wp,
                                         const float* __restrict__ bias,
                                         float* __restrict__ Out, int t) {
    int n0 = (t >> 5) * 8;
    int c0 = (t & 31) * 4;
    u64 acc[8][4];
#pragma unroll
    for (int i = 0; i < 8; i++) { acc[i][0] = 0; acc[i][1] = 0; acc[i][2] = 0; acc[i][3] = 0; }
#pragma unroll 4
    for (int kp = 0; kp < KP; kp++) {
        const u64* wr = Wp + kp * 128 + c0;
        ulonglong2 wa = *(const ulonglong2*)(wr);
        ulonglong2 wb = *(const ulonglong2*)(wr + 2);
        u64 xv[8];
#pragma unroll
        for (int i = 0; i < 8; i++) xv[i] = *(const u64*)(Xin + (n0 + i) * xs + 2 * kp);
#pragma unroll
        for (int i = 0; i < 8; i++) {
            fma2(acc[i][0], xv[i], wa.x);
            fma2(acc[i][1], xv[i], wa.y);
            fma2(acc[i][2], xv[i], wb.x);
            fma2(acc[i][3], xv[i], wb.y);
        }
    }
    float4 b = *(const float4*)(bias + c0);
#pragma unroll
    for (int i = 0; i < 8; i++) {
        float4 r;
        r.x = elu1(hadd(acc[i][0]) + b.x);
        r.y = elu1(hadd(acc[i][1]) + b.y);
        r.z = elu1(hadd(acc[i][2]) + b.z);
        r.w = elu1(hadd(acc[i][3]) + b.w);
        *(float4*)(Out + (n0 + i) * NPAD + c0) = r;
    }
}

// Convert fp32 tile (stride NPAD) -> packed bf16 hi/lo planes in Xp. 256 threads, 32 cols each.
__device__ __forceinline__ void convert_planes(const float* __restrict__ src0,
                                               unsigned* __restrict__ Xp, int t) {
    int n = t >> 2, cb = (t & 3) * 32;
    unsigned* xph = Xp + n * XPS + cb / 2;
    unsigned* xpl = xph + 64 * XPS;
    const float* src = src0 + n * NPAD + cb;
#pragma unroll
    for (int i = 0; i < 8; i++) {
        float4 v = *(const float4*)(src + i * 4);
        __nv_bfloat162 h01 = __floats2bfloat162_rn(v.x, v.y);
        __nv_bfloat162 h23 = __floats2bfloat162_rn(v.z, v.w);
        float2 hf01 = __bfloat1622float2(h01);
        float2 hf23 = __bfloat1622float2(h23);
        __nv_bfloat162 l01 = __floats2bfloat162_rn(v.x - hf01.x, v.y - hf01.y);
        __nv_bfloat162 l23 = __floats2bfloat162_rn(v.z - hf23.x, v.w - hf23.y);
        xph[i * 2]     = *reinterpret_cast<unsigned*>(&h01);
        xph[i * 2 + 1] = *reinterpret_cast<unsigned*>(&h23);
        xpl[i * 2]     = *reinterpret_cast<unsigned*>(&l01);
        xpl[i * 2 + 1] = *reinterpret_cast<unsigned*>(&l23);
    }
}

// Stage-1 W2 on tensor cores (3-term bf16 split): Out = elu(h1 @ W2 + b2).
// 8 warps: rows 16*(w&3), ntile half (w>>2)*8. 32 acc regs.
__device__ __forceinline__ void w2_mma(const unsigned* __restrict__ Xp,
                                       const float* __restrict__ b2,
                                       float* __restrict__ Out, int t) {
    int w = t >> 5, L = t & 31;
    int m0 = (w & 3) * 16;
    int nt0 = (w >> 2) * 8;
    const unsigned* xh = Xp + (m0 + (L >> 2)) * XPS + (L & 3);
    const unsigned* xl = xh + 64 * XPS;
    float acc[8][4];
#pragma unroll
    for (int q = 0; q < 8; q++) {
        acc[q][0] = 0.f; acc[q][1] = 0.f; acc[q][2] = 0.f; acc[q][3] = 0.f;
    }
    const unsigned* wb = g_W2f + L * 2;
#pragma unroll
    for (int ks = 0; ks < 8; ks++) {
        unsigned ah[4], al[4];
        ah[0] = xh[ks * 8];         ah[1] = xh[8 * XPS + ks * 8];
        ah[2] = xh[ks * 8 + 4];     ah[3] = xh[8 * XPS + ks * 8 + 4];
        al[0] = xl[ks * 8];         al[1] = xl[8 * XPS + ks * 8];
        al[2] = xl[ks * 8 + 4];     al[3] = xl[8 * XPS + ks * 8 + 4];
#pragma unroll
        for (int q = 0; q < 8; q++) {
            const unsigned* wp = wb + (ks * 16 + nt0 + q) * 64;
            uint2 bh = *(const uint2*)(wp);
            uint2 bl = *(const uint2*)(wp + 8192);
            mma_bf16(acc[q], ah, bh.x, bh.y);
            mma_bf16(acc[q], ah, bl.x, bl.y);
            mma_bf16(acc[q], al, bh.x, bh.y);
        }
    }
    int row = m0 + (L >> 2);
    int col0 = (L & 3) * 2;
#pragma unroll
    for (int q = 0; q < 8; q++) {
        int c = (nt0 + q) * 8 + col0;
        Out[row * NPAD + c]           = elu1(acc[q][0] + b2[c]);
        Out[row * NPAD + c + 1]       = elu1(acc[q][1] + b2[c + 1]);
        Out[(row + 8) * NPAD + c]     = elu1(acc[q][2] + b2[c]);
        Out[(row + 8) * NPAD + c + 1] = elu1(acc[q][3] + b2[c + 1]);
    }
}

// Distance Gram on tensor cores (4-term bf16 split). 8 warps: rows 16*(w&3), cols 32*(w>>2).
// Writes RAW fp32 distances into dsf (Xs window).
__device__ __forceinline__ void dist_mma(const unsigned* __restrict__ Xp,
                                         const float* __restrict__ sq,
                                         float* __restrict__ dsf, int t) {
    int w = t >> 5, L = t & 31;
    int m0 = (w & 3) * 16;
    int nbase = (w >> 2) * 32;
    const unsigned* xh = Xp + (m0 + (L >> 2)) * XPS + (L & 3);
    const unsigned* xl = xh + 64 * XPS;
    const unsigned* bbase = Xp + (nbase + (L >> 2)) * XPS + (L & 3);
    float acc[4][4];
#pragma unroll
    for (int nt = 0; nt < 4; nt++) {
        acc[nt][0] = 0.f; acc[nt][1] = 0.f; acc[nt][2] = 0.f; acc[nt][3] = 0.f;
    }
#pragma unroll
    for (int ks = 0; ks < 8; ks++) {
        unsigned ah[4], al[4];
        ah[0] = xh[ks * 8];         ah[1] = xh[8 * XPS + ks * 8];
        ah[2] = xh[ks * 8 + 4];     ah[3] = xh[8 * XPS + ks * 8 + 4];
        al[0] = xl[ks * 8];         al[1] = xl[8 * XPS + ks * 8];
        al[2] = xl[ks * 8 + 4];     al[3] = xl[8 * XPS + ks * 8 + 4];
#pragma unroll
        for (int nt = 0; nt < 4; nt++) {
            const unsigned* bh = bbase + nt * 8 * XPS + ks * 8;
            const unsigned* bl = bh + 64 * XPS;
            unsigned bh0 = bh[0], bh1 = bh[4];
            unsigned bl0 = bl[0], bl1 = bl[4];
            mma_bf16(acc[nt], ah, bh0, bh1);
            mma_bf16(acc[nt], ah, bl0, bl1);
            mma_bf16(acc[nt], al, bh0, bh1);
            mma_bf16(acc[nt], al, bl0, bl1);
        }
    }
    int r0 = m0 + (L >> 2);
    float si0 = sq[r0], si1 = sq[r0 + 8];
#pragma unroll
    for (int nt = 0; nt < 4; nt++) {
        int c0 = nbase + nt * 8 + (L & 3) * 2;
        float sj0 = sq[c0], sj1 = sq[c0 + 1];
        dsf[r0 * DPAD + c0]           = si0 + sj0 - 2.f * acc[nt][0];
        dsf[r0 * DPAD + c0 + 1]       = si0 + sj1 - 2.f * acc[nt][1];
        dsf[(r0 + 8) * DPAD + c0]     = si1 + sj0 - 2.f * acc[nt][2];
        dsf[(r0 + 8) * DPAD + c0 + 1] = si1 + sj1 - 2.f * acc[nt][3];
    }
}

// Edge gemm on tensor cores (3-term bf16 split). 8 warps: part=w>>2, rows 16*(w&3), 16 ntiles.
// Internal barrier before epilogue (covers dist's + edge's Xp reads).
__device__ void gemm_edge_mma(const unsigned* __restrict__ Xp,
                              float* __restrict__ Aout,
                              float* __restrict__ Pout, int t) {
    int w = t >> 5, L = t & 31;
    int part = w >> 2;
    int m0 = (w & 3) * 16;
    const unsigned* xh = Xp + (m0 + (L >> 2)) * XPS + (L & 3);
    const unsigned* xl = xh + 64 * XPS;
    float acc[16][4];
#pragma unroll
    for (int nt = 0; nt < 16; nt++) {
        acc[nt][0] = 0.f; acc[nt][1] = 0.f; acc[nt][2] = 0.f; acc[nt][3] = 0.f;
    }
    const unsigned* wb = g_Wfe + part * 16384 + L * 2;
#pragma unroll
    for (int ks = 0; ks < 8; ks++) {
        unsigned ah[4], al[4];
        ah[0] = xh[ks * 8];         ah[1] = xh[8 * XPS + ks * 8];
        ah[2] = xh[ks * 8 + 4];     ah[3] = xh[8 * XPS + ks * 8 + 4];
        al[0] = xl[ks * 8];         al[1] = xl[8 * XPS + ks * 8];
        al[2] = xl[ks * 8 + 4];     al[3] = xl[8 * XPS + ks * 8 + 4];
#pragma unroll
        for (int nt = 0; nt < 16; nt++) {
            const unsigned* wp = wb + (ks * 16 + nt) * 64;
            uint2 bh = *(const uint2*)(wp);
            uint2 bl = *(const uint2*)(wp + 8192);
            mma_bf16(acc[nt], ah, bh.x, bh.y);   // hi*hi
            mma_bf16(acc[nt], ah, bl.x, bl.y);   // hi*lo
            mma_bf16(acc[nt], al, bh.x, bh.y);   // lo*hi
        }
    }
    __syncthreads();   // all Xp reads (dist + edge) done; safe to overwrite Ap and Ps
    float* dst = part ? Pout : Aout;
    int row = m0 + (L >> 2);
    int col0 = (L & 3) * 2;
#pragma unroll
    for (int nt = 0; nt < 16; nt++) {
        *(float2*)(dst + row * NPAD + nt * 8 + col0)       = make_float2(acc[nt][0], acc[nt][1]);
        *(float2*)(dst + (row + 8) * NPAD + nt * 8 + col0) = make_float2(acc[nt][2], acc[nt][3]);
    }
}

// smem layout (floats)
#define OFF_XS  0                      // Xs fp32 features / distance matrix
#define OFF_AP  (NN * NPAD)            // Ap: 'a' fp32 / bf16 Xp planes / Xi scratch
#define OFF_PS  (2 * NN * NPAD)        // Ps: 'p' fp32 / h1 scratch
#define OFF_IDX (3 * NN * NPAD)
#define SMEM_FLOATS (OFF_IDX + NN * KNN + NN + 256)

__global__ __launch_bounds__(NT, 2)
void net_kernel(const float* __restrict__ x_pf,
                const float* __restrict__ b1, const float* __restrict__ b2,
                const float* __restrict__ bc,
                const float* __restrict__ Wo1, const float* __restrict__ bo1,
                const float* __restrict__ Wo2, const float* __restrict__ bo2,
                const float* __restrict__ Wo3, const float* __restrict__ bo3,
                const float* __restrict__ Wo4, const float* __restrict__ bo4,
                float* __restrict__ out, int write_batch) {
    extern __shared__ __align__(16) float sm[];
    float* Xs = sm + OFF_XS;
    float* Ap = sm + OFF_AP;
    float* Ps = sm + OFF_PS;
    int*   idxs = (int*)(sm + OFF_IDX);
    float* sq = sm + OFF_IDX + NN * KNN;
    float* hd = sq + NN;
    float* dsf = Xs;                   // fp32 distance matrix in Xs window
    unsigned* Xp  = (unsigned*)Ap;     // bf16 planes in Ap window

    int g = blockIdx.x;
    int t = threadIdx.x;

    // ---------------- Stage 1: h = elu(elu(x@W1+b1)@W2+b2) ----------------
    float* Xi = Ap;  // temp [64][16], col 15 zeroed
    for (int i = t; i < NN * 16; i += NT) {
        int n = i >> 4, f = i & 15;
        Xi[i] = (f < 15) ? x_pf[(g * NN + n) * 15 + f] : 0.f;
    }
    __syncthreads();
    gemm_act(Xi, 16, 8, g_W1p, b1, Ps, t);   // h1 (elu) -> Ps
    __syncthreads();
    convert_planes(Ps, Xp, t);               // h1 -> bf16 planes (Ap window; Xi dead)
    __syncthreads();
    w2_mma(Xp, b2, Xs, t);                   // h (elu) -> Xs

    // ---------------- 3 x EdgeConv ----------------
    for (int layer = 0; layer < 3; layer++) {
        __syncthreads();  // Xs ready; Ap free
        convert_planes(Xs, Xp, t);
        if (t < NN) {
            u64 a0 = 0, a1 = 0;
#pragma unroll 8
            for (int k4 = 0; k4 < 32; k4++) {
                ulonglong2 v = *(const ulonglong2*)(Xs + t * NPAD + k4 * 4);
                fma2(a0, v.x, v.x);
                fma2(a1, v.y, v.y);
            }
            sq[t] = hadd(a0) + hadd(a1);
        }
        __syncthreads();
        // merged MMA phase: dist writes fp32 distances over dead Xs, edge accumulates,
        // internal barrier (inside gemm_edge_mma), then edge writes Ap/Ps.
        dist_mma(Xp, sq, dsf, t);
        gemm_edge_mma(Xp, Ap, Ps, t);
        __syncthreads();
        // exact top-K by rank counting on fp32 keys:
        // FSETP (fma pipe) + predicated IADD (alu pipe) -> 2x pipe throughput vs int keys
        {
            int i = t >> 2, jb = (t & 3) * 16;
            const float* drow = dsf + i * DPAD;
            float kj[16];
#pragma unroll
            for (int q = 0; q < 4; q++) {
                float4 v = *(const float4*)(drow + jb + q * 4);
                kj[q * 4] = v.x; kj[q * 4 + 1] = v.y; kj[q * 4 + 2] = v.z; kj[q * 4 + 3] = v.w;
            }
            int rk[16];
#pragma unroll
            for (int jj = 0; jj < 16; jj++) rk[jj] = 0;
#pragma unroll 4
            for (int m4 = 0; m4 < 16; m4++) {
                float4 km = *(const float4*)(drow + m4 * 4);
#pragma unroll
                for (int jj = 0; jj < 16; jj++) {
                    rk[jj] += (km.x < kj[jj]) ? 1 : 0;
                    rk[jj] += (km.y < kj[jj]) ? 1 : 0;
                    rk[jj] += (km.z < kj[jj]) ? 1 : 0;
                    rk[jj] += (km.w < kj[jj]) ? 1 : 0;
                }
            }
#pragma unroll
            for (int jj = 0; jj < 16; jj++)
                if (rk[jj] < KNN) idxs[i * KNN + rk[jj]] = jb + jj;
        }
        __syncthreads();
        // gather-max: warp-per-node, full contiguous rows; writes Xs over dead distances
        {
            int w = t >> 5, lane = t & 31;
#pragma unroll
            for (int p = 0; p < 4; p++) {
                int n0 = w * 8 + 2 * p;
                int n1 = n0 + 1;
                float4 m0 = make_float4(-3.4e38f, -3.4e38f, -3.4e38f, -3.4e38f);
                float4 m1 = m0;
#pragma unroll 6
                for (int k = 0; k < KNN; k++) {
                    int i0 = idxs[n0 * KNN + k];
                    int i1 = idxs[n1 * KNN + k];
                    float4 v0 = *(const float4*)(Ps + i0 * NPAD + lane * 4);
                    float4 v1 = *(const float4*)(Ps + i1 * NPAD + lane * 4);
                    m0.x = fmaxf(m0.x, v0.x); m0.y = fmaxf(m0.y, v0.y);
                    m0.z = fmaxf(m0.z, v0.z); m0.w = fmaxf(m0.w, v0.w);
                    m1.x = fmaxf(m1.x, v1.x); m1.y = fmaxf(m1.y, v1.y);
                    m1.z = fmaxf(m1.z, v1.z); m1.w = fmaxf(m1.w, v1.w);
                }
                float4 a0 = *(const float4*)(Ap + n0 * NPAD + lane * 4);
                float4 a1 = *(const float4*)(Ap + n1 * NPAD + lane * 4);
                float4 bcv = *(const float4*)(bc + lane * 4);
                float4 r0, r1;
                r0.x = elu1(m0.x + a0.x + bcv.x);
                r0.y = elu1(m0.y + a0.y + bcv.y);
                r0.z = elu1(m0.z + a0.z + bcv.z);
                r0.w = elu1(m0.w + a0.w + bcv.w);
                r1.x = elu1(m1.x + a1.x + bcv.x);
                r1.y = elu1(m1.y + a1.y + bcv.y);
                r1.z = elu1(m1.z + a1.z + bcv.z);
                r1.w = elu1(m1.w + a1.w + bcv.w);
                *(float4*)(Xs + n0 * NPAD + lane * 4) = r0;
                *(float4*)(Xs + n1 * NPAD + lane * 4) = r1;
            }
        }
    }
    __syncthreads();

    // ---------------- pool + head MLP ----------------
    float* pooled = hd;        // 128
    float* o1 = hd + 128;      // 64
    float* o2 = hd + 192;      // 32
    float* o3 = hd + 224;      // 32
    if (t < 128) {
        float s = 0.f;
#pragma unroll 8
        for (int n = 0; n < NN; n++) s += Xs[n * NPAD + t];
        pooled[t] = s;
    }
    __syncthreads();
    if (t < 64) {
        float s = bo1[t];
        for (int k = 0; k < 128; k++) s = fmaf(pooled[k], Wo1[k * 64 + t], s);
        o1[t] = elu1(s);
    }
    __syncthreads();
    if (t < 32) {
        float s = bo2[t];
        for (int k = 0; k < 64; k++) s = fmaf(o1[k], Wo2[k * 32 + t], s);
        o2[t] = elu1(s);
    }
    __syncthreads();
    if (t < 32) {
        float s = bo3[t];
        for (int k = 0; k < 32; k++) s = fmaf(o2[k], Wo3[k * 32 + t], s);
        o3[t] = elu1(s);
    }
    __syncthreads();
    if (t < 8) {
        float s = bo4[t];
        for (int k = 0; k < 32; k++) s = fmaf(o3[k], Wo4[k * 8 + t], s);
        out[g * 8 + t] = s;
    }
    if (write_batch) {
        for (int l = t; l < NN; l += NT)
            out[NG * 8 + g * NN + l] = (float)g;
    }
}

static const int SMEM_BYTES = SMEM_FLOATS * 4;  // 108800

extern "C" void kernel_launch(void* const* d_in, const int* in_sizes, int n_in,
                              void* d_out, int out_size) {
    const float* x_pf = (const float*)d_in[0];
    // d_in[1] = batch_pf (implicit: node n belongs to graph n/64)
    const float* W1  = (const float*)d_in[2];
    const float* b1  = (const float*)d_in[3];
    const float* W2  = (const float*)d_in[4];
    const float* b2  = (const float*)d_in[5];
    const float* Wc  = (const float*)d_in[6];
    const float* bc  = (const float*)d_in[7];
    const float* Wo1 = (const float*)d_in[8];
    const float* bo1 = (const float*)d_in[9];
    const float* Wo2 = (const float*)d_in[10];
    const float* bo2 = (const float*)d_in[11];
    const float* Wo3 = (const float*)d_in[12];
    const float* bo3 = (const float*)d_in[13];
    const float* Wo4 = (const float*)d_in[14];
    const float* bo4 = (const float*)d_in[15];

    cudaFuncSetAttribute(net_kernel, cudaFuncAttributeMaxDynamicSharedMemorySize, SMEM_BYTES);

    prep_kernel<<<196, 256>>>(Wc, W1, W2);

    int write_batch = (out_size >= NG * 8 + NG * NN) ? 1 : 0;
    net_kernel<<<NG, NT, SMEM_BYTES>>>(x_pf, b1, b2, bc,
                                       Wo1, bo1, Wo2, bo2, Wo3, bo3, Wo4, bo4,
                                       (float*)d_out, write_batch);
}

// round 13
// speedup vs baseline: 2.2958x; 1.0439x over previous
#include <cuda_runtime.h>
#include <cuda_bf16.h>

typedef unsigned long long u64;

#define NG   256
#define NN   64
#define KNN  24
#define HID  128
#define NPAD 132   // float stride for fp32 64x128 tiles
#define DPAD 68    // float stride for 64x64 distance matrix
#define XPS  66    // u32 stride for packed bf16 planes
#define NT   256   // threads per CTA

// fragment-ordered bf16 edge weights: [part 2][split 2][kstep 8][ntile 16][lane 32][2] u32
__device__ __align__(16) unsigned g_Wfe[2 * 2 * 8 * 16 * 32 * 2];
// fragment-ordered bf16 W2: [split 2][kstep 8][ntile 16][lane 32][2] u32
__device__ __align__(16) unsigned g_W2f[2 * 8 * 16 * 32 * 2];
// k-pair-packed fp32 W1 (K=15 padded to 16)
__device__ u64 g_W1p[8 * 128];

__device__ __forceinline__ void fma2(u64& d, u64 a, u64 b) {
    asm("fma.rn.f32x2 %0, %1, %2, %0;" : "+l"(d) : "l"(a), "l"(b));
}
__device__ __forceinline__ float2 upk(u64 v) {
    float2 f; asm("mov.b64 {%0, %1}, %2;" : "=f"(f.x), "=f"(f.y) : "l"(v)); return f;
}
__device__ __forceinline__ u64 pk(float lo, float hi) {
    u64 r; asm("mov.b64 %0, {%1, %2};" : "=l"(r) : "f"(lo), "f"(hi)); return r;
}
__device__ __forceinline__ float hadd(u64 v) {
    float2 f = upk(v); return f.x + f.y;
}
__device__ __forceinline__ float elu1(float x) {
    return x > 0.f ? x : (__expf(x) - 1.f);
}
__device__ __forceinline__ unsigned pkbf2(float a, float b) {
    __nv_bfloat162 h = __floats2bfloat162_rn(a, b);
    return *reinterpret_cast<unsigned*>(&h);
}
__device__ __forceinline__ float bf16f(float v) {
    return __bfloat162float(__float2bfloat16_rn(v));
}

__device__ __forceinline__ void mma_bf16(float* c, const unsigned* a, unsigned b0, unsigned b1) {
    asm volatile("mma.sync.aligned.m16n8k16.row.col.f32.bf16.bf16.f32 "
        "{%0,%1,%2,%3}, {%4,%5,%6,%7}, {%8,%9}, {%0,%1,%2,%3};\n"
        : "+f"(c[0]), "+f"(c[1]), "+f"(c[2]), "+f"(c[3])
        : "r"(a[0]), "r"(a[1]), "r"(a[2]), "r"(a[3]), "r"(b0), "r"(b1));
}

// Wcat(k, cc): cc<128 -> Wc_top - Wc_bot ('a' weights); else Wc_bot ('p' weights)
__device__ __forceinline__ float wcat(const float* Wc, int k, int cc) {
    if (cc < HID) return Wc[k * HID + cc] - Wc[(HID + k) * HID + cc];
    return Wc[(HID + k) * HID + (cc - HID)];
}

__global__ void prep_kernel(const float* __restrict__ Wc,
                            const float* __restrict__ W1,
                            const float* __restrict__ W2) {
    int i = blockIdx.x * blockDim.x + threadIdx.x;
    if (i < 32768) {
        int r = i & 1, L = (i >> 1) & 31, nt = (i >> 6) & 15;
        int ks = (i >> 10) & 7, sp = (i >> 13) & 1, part = (i >> 14) & 1;
        int c  = nt * 8 + (L >> 2);
        int k0 = ks * 16 + (L & 3) * 2 + r * 8;
        int cc = part * HID + c;
        float v0 = wcat(Wc, k0, cc);
        float v1 = wcat(Wc, k0 + 1, cc);
        unsigned u;
        if (sp == 0) u = pkbf2(v0, v1);
        else         u = pkbf2(v0 - bf16f(v0), v1 - bf16f(v1));
        g_Wfe[i] = u;
    }
    int j = i - 32768;
    if (j >= 0 && j < 16384) {
        int r = j & 1, L = (j >> 1) & 31, nt = (j >> 6) & 15;
        int ks = (j >> 10) & 7, sp = (j >> 13) & 1;
        int c  = nt * 8 + (L >> 2);
        int k0 = ks * 16 + (L & 3) * 2 + r * 8;
        float v0 = W2[k0 * HID + c];
        float v1 = W2[(k0 + 1) * HID + c];
        unsigned u;
        if (sp == 0) u = pkbf2(v0, v1);
        else         u = pkbf2(v0 - bf16f(v0), v1 - bf16f(v1));
        g_W2f[j] = u;
    }
    int l = i - 32768 - 16384;
    if (l >= 0 && l < 8 * 128) {
        int kp = l >> 7, c = l & 127;
        float lo = W1[(2 * kp) * HID + c];
        float hi = (2 * kp + 1 < 15) ? W1[(2 * kp + 1) * HID + c] : 0.f;
        g_W1p[l] = pk(lo, hi);
    }
}

// Out[64x128] = elu( Xin[64 x 2*KP] @ W + bias ). 256 threads, 8 rows x 4 cols per thread.
__device__ __forceinline__ void gemm_act(const float* __restrict__ Xin, int xs, int KP,
                                         const u64* __restrict__ Wp,
                                         const float* __restrict__ bias,
                                         float* __restrict__ Out, int t) {
    int n0 = (t >> 5) * 8;
    int c0 = (t & 31) * 4;
    u64 acc[8][4];
#pragma unroll
    for (int i = 0; i < 8; i++) { acc[i][0] = 0; acc[i][1] = 0; acc[i][2] = 0; acc[i][3] = 0; }
#pragma unroll 4
    for (int kp = 0; kp < KP; kp++) {
        const u64* wr = Wp + kp * 128 + c0;
        ulonglong2 wa = *(const ulonglong2*)(wr);
        ulonglong2 wb = *(const ulonglong2*)(wr + 2);
        u64 xv[8];
#pragma unroll
        for (int i = 0; i < 8; i++) xv[i] = *(const u64*)(Xin + (n0 + i) * xs + 2 * kp);
#pragma unroll
        for (int i = 0; i < 8; i++) {
            fma2(acc[i][0], xv[i], wa.x);
            fma2(acc[i][1], xv[i], wa.y);
            fma2(acc[i][2], xv[i], wb.x);
            fma2(acc[i][3], xv[i], wb.y);
        }
    }
    float4 b = *(const float4*)(bias + c0);
#pragma unroll
    for (int i = 0; i < 8; i++) {
        float4 r;
        r.x = elu1(hadd(acc[i][0]) + b.x);
        r.y = elu1(hadd(acc[i][1]) + b.y);
        r.z = elu1(hadd(acc[i][2]) + b.z);
        r.w = elu1(hadd(acc[i][3]) + b.w);
        *(float4*)(Out + (n0 + i) * NPAD + c0) = r;
    }
}

// Convert fp32 tile (stride NPAD) -> packed bf16 hi/lo planes in Xp, with fused
// squared-norm: partial v.v per thread, quad shuffle-reduce, lane (t&3)==0 writes sq[n].
__device__ __forceinline__ void convert_planes(const float* __restrict__ src0,
                                               unsigned* __restrict__ Xp,
                                               float* __restrict__ sq, int t) {
    int n = t >> 2, cb = (t & 3) * 32;
    unsigned* xph = Xp + n * XPS + cb / 2;
    unsigned* xpl = xph + 64 * XPS;
    const float* src = src0 + n * NPAD + cb;
    float s = 0.f;
#pragma unroll
    for (int i = 0; i < 8; i++) {
        float4 v = *(const float4*)(src + i * 4);
        s = fmaf(v.x, v.x, s); s = fmaf(v.y, v.y, s);
        s = fmaf(v.z, v.z, s); s = fmaf(v.w, v.w, s);
        __nv_bfloat162 h01 = __floats2bfloat162_rn(v.x, v.y);
        __nv_bfloat162 h23 = __floats2bfloat162_rn(v.z, v.w);
        float2 hf01 = __bfloat1622float2(h01);
        float2 hf23 = __bfloat1622float2(h23);
        __nv_bfloat162 l01 = __floats2bfloat162_rn(v.x - hf01.x, v.y - hf01.y);
        __nv_bfloat162 l23 = __floats2bfloat162_rn(v.z - hf23.x, v.w - hf23.y);
        *(uint2*)(xph + i * 2) = make_uint2(*reinterpret_cast<unsigned*>(&h01),
                                            *reinterpret_cast<unsigned*>(&h23));
        *(uint2*)(xpl + i * 2) = make_uint2(*reinterpret_cast<unsigned*>(&l01),
                                            *reinterpret_cast<unsigned*>(&l23));
    }
    s += __shfl_xor_sync(0xffffffffu, s, 1);
    s += __shfl_xor_sync(0xffffffffu, s, 2);
    if ((t & 3) == 0) sq[n] = s;
}

// Stage-1 W2 on tensor cores (3-term bf16 split): Out = elu(h1 @ W2 + b2).
// 8 warps: rows 16*(w&3), ntile half (w>>2)*8. 32 acc regs.
__device__ __forceinline__ void w2_mma(const unsigned* __restrict__ Xp,
                                       const float* __restrict__ b2,
                                       float* __restrict__ Out, int t) {
    int w = t >> 5, L = t & 31;
    int m0 = (w & 3) * 16;
    int nt0 = (w >> 2) * 8;
    const unsigned* xh = Xp + (m0 + (L >> 2)) * XPS + (L & 3);
    const unsigned* xl = xh + 64 * XPS;
    float acc[8][4];
#pragma unroll
    for (int q = 0; q < 8; q++) {
        acc[q][0] = 0.f; acc[q][1] = 0.f; acc[q][2] = 0.f; acc[q][3] = 0.f;
    }
    const unsigned* wb = g_W2f + L * 2;
#pragma unroll
    for (int ks = 0; ks < 8; ks++) {
        unsigned ah[4], al[4];
        ah[0] = xh[ks * 8];         ah[1] = xh[8 * XPS + ks * 8];
        ah[2] = xh[ks * 8 + 4];     ah[3] = xh[8 * XPS + ks * 8 + 4];
        al[0] = xl[ks * 8];         al[1] = xl[8 * XPS + ks * 8];
        al[2] = xl[ks * 8 + 4];     al[3] = xl[8 * XPS + ks * 8 + 4];
#pragma unroll
        for (int q = 0; q < 8; q++) {
            const unsigned* wp = wb + (ks * 16 + nt0 + q) * 64;
            uint2 bh = *(const uint2*)(wp);
            uint2 bl = *(const uint2*)(wp + 8192);
            mma_bf16(acc[q], ah, bh.x, bh.y);
            mma_bf16(acc[q], ah, bl.x, bl.y);
            mma_bf16(acc[q], al, bh.x, bh.y);
        }
    }
    int row = m0 + (L >> 2);
    int col0 = (L & 3) * 2;
#pragma unroll
    for (int q = 0; q < 8; q++) {
        int c = (nt0 + q) * 8 + col0;
        Out[row * NPAD + c]           = elu1(acc[q][0] + b2[c]);
        Out[row * NPAD + c + 1]       = elu1(acc[q][1] + b2[c + 1]);
        Out[(row + 8) * NPAD + c]     = elu1(acc[q][2] + b2[c]);
        Out[(row + 8) * NPAD + c + 1] = elu1(acc[q][3] + b2[c + 1]);
    }
}

// Distance Gram on tensor cores (4-term bf16 split). 8 warps: rows 16*(w&3), cols 32*(w>>2).
// Writes RAW fp32 distances into dsf (Xs window).
__device__ __forceinline__ void dist_mma(const unsigned* __restrict__ Xp,
                                         const float* __restrict__ sq,
                                         float* __restrict__ dsf, int t) {
    int w = t >> 5, L = t & 31;
    int m0 = (w & 3) * 16;
    int nbase = (w >> 2) * 32;
    const unsigned* xh = Xp + (m0 + (L >> 2)) * XPS + (L & 3);
    const unsigned* xl = xh + 64 * XPS;
    const unsigned* bbase = Xp + (nbase + (L >> 2)) * XPS + (L & 3);
    float acc[4][4];
#pragma unroll
    for (int nt = 0; nt < 4; nt++) {
        acc[nt][0] = 0.f; acc[nt][1] = 0.f; acc[nt][2] = 0.f; acc[nt][3] = 0.f;
    }
#pragma unroll
    for (int ks = 0; ks < 8; ks++) {
        unsigned ah[4], al[4];
        ah[0] = xh[ks * 8];         ah[1] = xh[8 * XPS + ks * 8];
        ah[2] = xh[ks * 8 + 4];     ah[3] = xh[8 * XPS + ks * 8 + 4];
        al[0] = xl[ks * 8];         al[1] = xl[8 * XPS + ks * 8];
        al[2] = xl[ks * 8 + 4];     al[3] = xl[8 * XPS + ks * 8 + 4];
#pragma unroll
        for (int nt = 0; nt < 4; nt++) {
            const unsigned* bh = bbase + nt * 8 * XPS + ks * 8;
            const unsigned* bl = bh + 64 * XPS;
            unsigned bh0 = bh[0], bh1 = bh[4];
            unsigned bl0 = bl[0], bl1 = bl[4];
            mma_bf16(acc[nt], ah, bh0, bh1);
            mma_bf16(acc[nt], ah, bl0, bl1);
            mma_bf16(acc[nt], al, bh0, bh1);
            mma_bf16(acc[nt], al, bl0, bl1);
        }
    }
    int r0 = m0 + (L >> 2);
    float si0 = sq[r0], si1 = sq[r0 + 8];
#pragma unroll
    for (int nt = 0; nt < 4; nt++) {
        int c0 = nbase + nt * 8 + (L & 3) * 2;
        float sj0 = sq[c0], sj1 = sq[c0 + 1];
        dsf[r0 * DPAD + c0]           = si0 + sj0 - 2.f * acc[nt][0];
        dsf[r0 * DPAD + c0 + 1]       = si0 + sj1 - 2.f * acc[nt][1];
        dsf[(r0 + 8) * DPAD + c0]     = si1 + sj0 - 2.f * acc[nt][2];
        dsf[(r0 + 8) * DPAD + c0 + 1] = si1 + sj1 - 2.f * acc[nt][3];
    }
}

// Edge gemm on tensor cores (3-term bf16 split). 8 warps: part=w>>2, rows 16*(w&3), 16 ntiles.
// Internal barrier before epilogue (covers dist's + edge's Xp reads).
__device__ void gemm_edge_mma(const unsigned* __restrict__ Xp,
                              float* __restrict__ Aout,
                              float* __restrict__ Pout, int t) {
    int w = t >> 5, L = t & 31;
    int part = w >> 2;
    int m0 = (w & 3) * 16;
    const unsigned* xh = Xp + (m0 + (L >> 2)) * XPS + (L & 3);
    const unsigned* xl = xh + 64 * XPS;
    float acc[16][4];
#pragma unroll
    for (int nt = 0; nt < 16; nt++) {
        acc[nt][0] = 0.f; acc[nt][1] = 0.f; acc[nt][2] = 0.f; acc[nt][3] = 0.f;
    }
    const unsigned* wb = g_Wfe + part * 16384 + L * 2;
#pragma unroll
    for (int ks = 0; ks < 8; ks++) {
        unsigned ah[4], al[4];
        ah[0] = xh[ks * 8];         ah[1] = xh[8 * XPS + ks * 8];
        ah[2] = xh[ks * 8 + 4];     ah[3] = xh[8 * XPS + ks * 8 + 4];
        al[0] = xl[ks * 8];         al[1] = xl[8 * XPS + ks * 8];
        al[2] = xl[ks * 8 + 4];     al[3] = xl[8 * XPS + ks * 8 + 4];
#pragma unroll
        for (int nt = 0; nt < 16; nt++) {
            const unsigned* wp = wb + (ks * 16 + nt) * 64;
            uint2 bh = *(const uint2*)(wp);
            uint2 bl = *(const uint2*)(wp + 8192);
            mma_bf16(acc[nt], ah, bh.x, bh.y);   // hi*hi
            mma_bf16(acc[nt], ah, bl.x, bl.y);   // hi*lo
            mma_bf16(acc[nt], al, bh.x, bh.y);   // lo*hi
        }
    }
    __syncthreads();   // all Xp reads (dist + edge) done; safe to overwrite Ap and Ps
    float* dst = part ? Pout : Aout;
    int row = m0 + (L >> 2);
    int col0 = (L & 3) * 2;
#pragma unroll
    for (int nt = 0; nt < 16; nt++) {
        *(float2*)(dst + row * NPAD + nt * 8 + col0)       = make_float2(acc[nt][0], acc[nt][1]);
        *(float2*)(dst + (row + 8) * NPAD + nt * 8 + col0) = make_float2(acc[nt][2], acc[nt][3]);
    }
}

// smem layout (floats)
#define OFF_XS  0                      // Xs fp32 features / distance matrix
#define OFF_AP  (NN * NPAD)            // Ap: 'a' fp32 / bf16 Xp planes / Xi scratch
#define OFF_PS  (2 * NN * NPAD)        // Ps: 'p' fp32 / h1 scratch
#define OFF_IDX (3 * NN * NPAD)
#define SMEM_FLOATS (OFF_IDX + NN * KNN + NN + 256)

__global__ __launch_bounds__(NT, 2)
void net_kernel(const float* __restrict__ x_pf,
                const float* __restrict__ b1, const float* __restrict__ b2,
                const float* __restrict__ bc,
                const float* __restrict__ Wo1, const float* __restrict__ bo1,
                const float* __restrict__ Wo2, const float* __restrict__ bo2,
                const float* __restrict__ Wo3, const float* __restrict__ bo3,
                const float* __restrict__ Wo4, const float* __restrict__ bo4,
                float* __restrict__ out, int write_batch) {
    extern __shared__ __align__(16) float sm[];
    float* Xs = sm + OFF_XS;
    float* Ap = sm + OFF_AP;
    float* Ps = sm + OFF_PS;
    int*   idxs = (int*)(sm + OFF_IDX);
    float* sq = sm + OFF_IDX + NN * KNN;
    float* hd = sq + NN;
    float* dsf = Xs;                   // fp32 distance matrix in Xs window
    unsigned* Xp  = (unsigned*)Ap;     // bf16 planes in Ap window

    int g = blockIdx.x;
    int t = threadIdx.x;

    // ---------------- Stage 1: h = elu(elu(x@W1+b1)@W2+b2) ----------------
    float* Xi = Ap;  // temp [64][16], col 15 zeroed
    for (int i = t; i < NN * 16; i += NT) {
        int n = i >> 4, f = i & 15;
        Xi[i] = (f < 15) ? x_pf[(g * NN + n) * 15 + f] : 0.f;
    }
    __syncthreads();
    gemm_act(Xi, 16, 8, g_W1p, b1, Ps, t);   // h1 (elu) -> Ps
    __syncthreads();
    convert_planes(Ps, Xp, sq, t);           // h1 -> bf16 planes (sq written but unused)
    __syncthreads();
    w2_mma(Xp, b2, Xs, t);                   // h (elu) -> Xs

    // ---------------- 3 x EdgeConv ----------------
    for (int layer = 0; layer < 3; layer++) {
        __syncthreads();  // Xs ready; Ap free
        convert_planes(Xs, Xp, sq, t);       // bf16 planes + fused squared norms
        __syncthreads();
        // merged MMA phase: dist writes fp32 distances over dead Xs, edge accumulates,
        // internal barrier (inside gemm_edge_mma), then edge writes Ap/Ps.
        dist_mma(Xp, sq, dsf, t);
        gemm_edge_mma(Xp, Ap, Ps, t);
        __syncthreads();
        // exact top-K by rank counting on fp32 keys (FSETP on fma pipe + IADD on alu pipe)
        {
            int i = t >> 2, jb = (t & 3) * 16;
            const float* drow = dsf + i * DPAD;
            float kj[16];
#pragma unroll
            for (int q = 0; q < 4; q++) {
                float4 v = *(const float4*)(drow + jb + q * 4);
                kj[q * 4] = v.x; kj[q * 4 + 1] = v.y; kj[q * 4 + 2] = v.z; kj[q * 4 + 3] = v.w;
            }
            int rk[16];
#pragma unroll
            for (int jj = 0; jj < 16; jj++) rk[jj] = 0;
#pragma unroll 4
            for (int m4 = 0; m4 < 16; m4++) {
                float4 km = *(const float4*)(drow + m4 * 4);
#pragma unroll
                for (int jj = 0; jj < 16; jj++) {
                    rk[jj] += (km.x < kj[jj]) ? 1 : 0;
                    rk[jj] += (km.y < kj[jj]) ? 1 : 0;
                    rk[jj] += (km.z < kj[jj]) ? 1 : 0;
                    rk[jj] += (km.w < kj[jj]) ? 1 : 0;
                }
            }
#pragma unroll
            for (int jj = 0; jj < 16; jj++)
                if (rk[jj] < KNN) idxs[i * KNN + rk[jj]] = jb + jj;
        }
        __syncthreads();
        // gather-max: warp-per-node, 4 nodes in flight (2x MLP vs R12); writes Xs
        {
            int w = t >> 5, lane = t & 31;
#pragma unroll
            for (int p = 0; p < 2; p++) {
                int nb = w * 8 + 4 * p;
                float4 mx[4];
#pragma unroll
                for (int q = 0; q < 4; q++)
                    mx[q] = make_float4(-3.4e38f, -3.4e38f, -3.4e38f, -3.4e38f);
#pragma unroll 4
                for (int k = 0; k < KNN; k++) {
#pragma unroll
                    for (int q = 0; q < 4; q++) {
                        int idx = idxs[(nb + q) * KNN + k];
                        float4 v = *(const float4*)(Ps + idx * NPAD + lane * 4);
                        mx[q].x = fmaxf(mx[q].x, v.x); mx[q].y = fmaxf(mx[q].y, v.y);
                        mx[q].z = fmaxf(mx[q].z, v.z); mx[q].w = fmaxf(mx[q].w, v.w);
                    }
                }
                float4 bcv = *(const float4*)(bc + lane * 4);
#pragma unroll
                for (int q = 0; q < 4; q++) {
                    int n = nb + q;
                    float4 a = *(const float4*)(Ap + n * NPAD + lane * 4);
                    float4 r;
                    r.x = elu1(mx[q].x + a.x + bcv.x);
                    r.y = elu1(mx[q].y + a.y + bcv.y);
                    r.z = elu1(mx[q].z + a.z + bcv.z);
                    r.w = elu1(mx[q].w + a.w + bcv.w);
                    *(float4*)(Xs + n * NPAD + lane * 4) = r;
                }
            }
        }
    }
    __syncthreads();

    // ---------------- pool + head MLP ----------------
    float* pooled = hd;        // 128
    float* o1 = hd + 128;      // 64
    float* o2 = hd + 192;      // 32
    float* o3 = hd + 224;      // 32
    if (t < 128) {
        float s = 0.f;
#pragma unroll 8
        for (int n = 0; n < NN; n++) s += Xs[n * NPAD + t];
        pooled[t] = s;
    }
    __syncthreads();
    if (t < 64) {
        float s = bo1[t];
        for (int k = 0; k < 128; k++) s = fmaf(pooled[k], Wo1[k * 64 + t], s);
        o1[t] = elu1(s);
    }
    __syncthreads();
    if (t < 32) {
        float s = bo2[t];
        for (int k = 0; k < 64; k++) s = fmaf(o1[k], Wo2[k * 32 + t], s);
        o2[t] = elu1(s);
    }
    __syncthreads();
    if (t < 32) {
        float s = bo3[t];
        for (int k = 0; k < 32; k++) s = fmaf(o2[k], Wo3[k * 32 + t], s);
        o3[t] = elu1(s);
    }
    __syncthreads();
    if (t < 8) {
        float s = bo4[t];
        for (int k = 0; k < 32; k++) s = fmaf(o3[k], Wo4[k * 8 + t], s);
        out[g * 8 + t] = s;
    }
    if (write_batch) {
        for (int l = t; l < NN; l += NT)
            out[NG * 8 + g * NN + l] = (float)g;
    }
}

static const int SMEM_BYTES = SMEM_FLOATS * 4;  // 108800

extern "C" void kernel_launch(void* const* d_in, const int* in_sizes, int n_in,
                              void* d_out, int out_size) {
    const float* x_pf = (const float*)d_in[0];
    // d_in[1] = batch_pf (implicit: node n belongs to graph n/64)
    const float* W1  = (const float*)d_in[2];
    const float* b1  = (const float*)d_in[3];
    const float* W2  = (const float*)d_in[4];
    const float* b2  = (const float*)d_in[5];
    const float* Wc  = (const float*)d_in[6];
    const float* bc  = (const float*)d_in[7];
    const float* Wo1 = (const float*)d_in[8];
    const float* bo1 = (const float*)d_in[9];
    const float* Wo2 = (const float*)d_in[10];
    const float* bo2 = (const float*)d_in[11];
    const float* Wo3 = (const float*)d_in[12];
    const float* bo3 = (const float*)d_in[13];
    const float* Wo4 = (const float*)d_in[14];
    const float* bo4 = (const float*)d_in[15];

    cudaFuncSetAttribute(net_kernel, cudaFuncAttributeMaxDynamicSharedMemorySize, SMEM_BYTES);

    prep_kernel<<<196, 256>>>(Wc, W1, W2);

    int write_batch = (out_size >= NG * 8 + NG * NN) ? 1 : 0;
    net_kernel<<<NG, NT, SMEM_BYTES>>>(x_pf, b1, b2, bc,
                                       Wo1, bo1, Wo2, bo2, Wo3, bo3, Wo4, bo4,
                                       (float*)d_out, write_batch);
}